// round 1
// baseline (speedup 1.0000x reference)
#include <cuda_runtime.h>
#include <math.h>

// ---------------------------------------------------------------------------
// Problem constants (fixed by the reference)
// ---------------------------------------------------------------------------
#define BB 4096           // batch of graphs
#define NN 19             // nodes per graph
#define EE 342            // directed edges (before self loops)
#define ET 361            // EE + NN self loops
#define FF 256            // input feature dim
#define HH 512            // hidden dim
#define OO 256            // last layer dim
#define MM (BB * NN)      // 77824 rows for the dense projections

// ---------------------------------------------------------------------------
// Scratch (device globals: no allocation allowed in kernel_launch)
// ---------------------------------------------------------------------------
__device__ float g_bufA[(size_t)MM * HH];
__device__ float g_bufB[(size_t)MM * HH];
__device__ int   g_offs[NN + 1];
__device__ int   g_perm[ET];   // edge ids sorted by dst
__device__ int   g_psrc[ET];   // src node of the dst-sorted edges

// ---------------------------------------------------------------------------
// CSR build: one thread, 361 edges. edge_index is [2, EE] int32; self loops
// appended (src=dst=n) exactly like the reference.
// ---------------------------------------------------------------------------
__global__ void build_csr(const int* __restrict__ ei) {
    int cnt[NN];
    for (int i = 0; i < NN; i++) cnt[i] = 0;
    for (int e = 0; e < ET; e++) {
        int d = (e < EE) ? ei[EE + e] : (e - EE);
        cnt[d]++;
    }
    int offs[NN + 1];
    offs[0] = 0;
    for (int i = 0; i < NN; i++) offs[i + 1] = offs[i] + cnt[i];
    for (int i = 0; i <= NN; i++) g_offs[i] = offs[i];
    int pos[NN];
    for (int i = 0; i < NN; i++) pos[i] = offs[i];
    for (int e = 0; e < ET; e++) {
        int s = (e < EE) ? ei[e] : (e - EE);
        int d = (e < EE) ? ei[EE + e] : (e - EE);
        int p = pos[d]++;
        g_perm[p] = e;
        g_psrc[p] = s;
    }
}

// ---------------------------------------------------------------------------
// fp32 SGEMM: C[M,N] = A[M,K] * B[K,N].   128x128 block, 8x8 microtile,
// K-step 8.  Requires M%128==0, N%128==0, K%8==0 (all hold here).
// ---------------------------------------------------------------------------
__global__ void __launch_bounds__(256) sgemm128(
    const float* __restrict__ A, const float* __restrict__ Bm,
    float* __restrict__ Cm, int M, int Nn, int K)
{
    __shared__ alignas(16) float As[8][136];   // As[k][m]  (transposed A tile)
    __shared__ alignas(16) float Bs[8][136];   // Bs[k][n]

    const int t  = threadIdx.x;
    const int tx = t & 15;
    const int ty = t >> 4;
    const int bm = blockIdx.y * 128;
    const int bn = blockIdx.x * 128;

    const int aRow = t >> 1;          // 0..127
    const int aK   = (t & 1) * 4;     // 0 or 4
    const int bRow = t >> 5;          // 0..7
    const int bCol = (t & 31) * 4;    // 0..124

    float acc[8][8];
#pragma unroll
    for (int i = 0; i < 8; i++)
#pragma unroll
        for (int j = 0; j < 8; j++) acc[i][j] = 0.f;

    for (int k0 = 0; k0 < K; k0 += 8) {
        float4 av = *(const float4*)(A  + (size_t)(bm + aRow) * K + k0 + aK);
        float4 bv = *(const float4*)(Bm + (size_t)(k0 + bRow) * Nn + bn + bCol);
        As[aK + 0][aRow] = av.x;
        As[aK + 1][aRow] = av.y;
        As[aK + 2][aRow] = av.z;
        As[aK + 3][aRow] = av.w;
        *(float4*)&Bs[bRow][bCol] = bv;
        __syncthreads();

#pragma unroll
        for (int kk = 0; kk < 8; kk++) {
            float a[8], b[8];
            *(float4*)(a)     = *(const float4*)&As[kk][ty * 4];
            *(float4*)(a + 4) = *(const float4*)&As[kk][64 + ty * 4];
            *(float4*)(b)     = *(const float4*)&Bs[kk][tx * 4];
            *(float4*)(b + 4) = *(const float4*)&Bs[kk][64 + tx * 4];
#pragma unroll
            for (int i = 0; i < 8; i++)
#pragma unroll
                for (int j = 0; j < 8; j++)
                    acc[i][j] += a[i] * b[j];
        }
        __syncthreads();
    }

#pragma unroll
    for (int qi = 0; qi < 2; qi++)
#pragma unroll
        for (int i = 0; i < 4; i++) {
            int row = bm + qi * 64 + ty * 4 + i;
            float* cp = Cm + (size_t)row * Nn + bn;
            float* ar = acc[qi * 4 + i];
            *(float4*)(cp + tx * 4)      = make_float4(ar[0], ar[1], ar[2], ar[3]);
            *(float4*)(cp + 64 + tx * 4) = make_float4(ar[4], ar[5], ar[6], ar[7]);
        }
}

// ---------------------------------------------------------------------------
// Per-graph attention + aggregation.  One CTA per graph, C threads.
// Stages: load h tile -> attention logits (warp dots) -> leaky_relu ->
// segment softmax over dst (smem atomics) -> CSR aggregation -> +bias,
// optional ReLU.  FINAL additionally computes
//   scores[n] = sigmoid( h4[n] . (sum_m ws[m] h4[m]) + bs )
// ---------------------------------------------------------------------------
__device__ __forceinline__ void atomicMaxF(float* addr, float v) {
    int* ai = (int*)addr;
    int old = __float_as_int(*addr);
    while (__int_as_float(old) < v) {
        int prev = atomicCAS(ai, old, __float_as_int(v));
        if (prev == old) break;
        old = prev;
    }
}

template <int C, bool RELU, bool FINAL>
__global__ void __launch_bounds__(C) gat_agg(
    const float* __restrict__ H, const int* __restrict__ ei,
    const float* __restrict__ a_s, const float* __restrict__ a_d,
    const float* __restrict__ bias, float* __restrict__ outp,
    const float* __restrict__ ws, const float* __restrict__ bsc)
{
    __shared__ alignas(16) float hs[NN * C];
    __shared__ float asv[C], adv[C];
    __shared__ float als[NN], ald[NN], nmax[NN], nsum[NN];
    __shared__ float ebuf[ET];
    __shared__ alignas(16) float outbuf[FINAL ? NN * C : 1];
    __shared__ float pbuf[FINAL ? C : 1];

    const int t = threadIdx.x;
    const size_t gbase = (size_t)blockIdx.x * NN * C;

    // stage 0: loads + init
    asv[t] = a_s[t];
    adv[t] = a_d[t];
    if (t < NN) { nmax[t] = -1e30f; nsum[t] = 0.f; }
    {
        const float4* H4 = (const float4*)(H + gbase);
        float4* hs4 = (float4*)hs;
        for (int i = t; i < NN * C / 4; i += C) hs4[i] = H4[i];
    }
    __syncthreads();

    // stage 1: per-node attention logits  als[n] = h[n].a_src, ald[n] = h[n].a_dst
    {
        const int w = t >> 5, lane = t & 31, NW = C / 32;
        for (int n = w; n < NN; n += NW) {
            float s = 0.f, d = 0.f;
#pragma unroll
            for (int j = 0; j < C / 32; j++) {
                float h = hs[n * C + lane + 32 * j];
                s += h * asv[lane + 32 * j];
                d += h * adv[lane + 32 * j];
            }
#pragma unroll
            for (int o = 16; o; o >>= 1) {
                s += __shfl_xor_sync(0xffffffffu, s, o);
                d += __shfl_xor_sync(0xffffffffu, d, o);
            }
            if (lane == 0) { als[n] = s; ald[n] = d; }
        }
    }
    __syncthreads();

    // stage 2: edge logits + leaky relu + segment max
    for (int e = t; e < ET; e += C) {
        int se = (e < EE) ? ei[e] : (e - EE);
        int de = (e < EE) ? ei[EE + e] : (e - EE);
        float z = als[se] + ald[de];
        float lg = (z >= 0.f) ? z : 0.2f * z;
        ebuf[e] = lg;
        atomicMaxF(&nmax[de], lg);
    }
    __syncthreads();

    // stage 3: exp + segment sum
    for (int e = t; e < ET; e += C) {
        int de = (e < EE) ? ei[EE + e] : (e - EE);
        float ex = expf(ebuf[e] - nmax[de]);
        ebuf[e] = ex;
        atomicAdd(&nsum[de], ex);
    }
    __syncthreads();

    // stage 4: alpha
    for (int e = t; e < ET; e += C) {
        int de = (e < EE) ? ei[EE + e] : (e - EE);
        ebuf[e] = ebuf[e] / nsum[de];
    }
    __syncthreads();

    // stage 5: aggregation over dst-sorted edges
    {
        const int c = t;
        const float bc = bias[c];
        for (int n = 0; n < NN; n++) {
            float acc = 0.f;
            const int e0 = g_offs[n], e1 = g_offs[n + 1];
            for (int i = e0; i < e1; i++) {
                acc += ebuf[g_perm[i]] * hs[g_psrc[i] * C + c];
            }
            float v = acc + bc;
            if (RELU) v = fmaxf(v, 0.f);
            if constexpr (!FINAL) {
                outp[gbase + (size_t)n * C + c] = v;
            } else {
                outbuf[n * C + c] = v;
            }
        }
    }

    if constexpr (FINAL) {
        __syncthreads();
        // p[c] = sum_n ws[n] * h4[n][c]
        {
            float pv = 0.f;
#pragma unroll
            for (int n = 0; n < NN; n++) pv += ws[n] * outbuf[n * C + t];
            pbuf[t] = pv;
        }
        __syncthreads();
        // scores[n] = sigmoid(h4[n].p + bs)
        {
            const int w = t >> 5, lane = t & 31, NW = C / 32;
            const float bv = bsc[0];
            for (int n = w; n < NN; n += NW) {
                float s = 0.f;
#pragma unroll
                for (int j = 0; j < C / 32; j++)
                    s += outbuf[n * C + lane + 32 * j] * pbuf[lane + 32 * j];
#pragma unroll
                for (int o = 16; o; o >>= 1)
                    s += __shfl_xor_sync(0xffffffffu, s, o);
                if (lane == 0)
                    outp[(size_t)blockIdx.x * NN + n] = 1.f / (1.f + expf(-(s + bv)));
            }
        }
    }
}

// ---------------------------------------------------------------------------
// Launch
// ---------------------------------------------------------------------------
extern "C" void kernel_launch(void* const* d_in, const int* in_sizes, int n_in,
                              void* d_out, int out_size)
{
    (void)in_sizes; (void)n_in; (void)out_size;
    const float* x   = (const float*)d_in[0];
    const int*   ei  = (const int*)  d_in[1];
    // d_in[2] = edge_attr (ignored; GATConv edge_dim=None)
    const float* W1  = (const float*)d_in[3];
    const float* as1 = (const float*)d_in[4];
    const float* ad1 = (const float*)d_in[5];
    const float* b1  = (const float*)d_in[6];
    const float* W2  = (const float*)d_in[7];
    const float* as2 = (const float*)d_in[8];
    const float* ad2 = (const float*)d_in[9];
    const float* b2  = (const float*)d_in[10];
    const float* W3  = (const float*)d_in[11];
    const float* as3 = (const float*)d_in[12];
    const float* ad3 = (const float*)d_in[13];
    const float* b3  = (const float*)d_in[14];
    const float* W4  = (const float*)d_in[15];
    const float* as4 = (const float*)d_in[16];
    const float* ad4 = (const float*)d_in[17];
    const float* b4  = (const float*)d_in[18];
    const float* ws  = (const float*)d_in[19];
    const float* bs  = (const float*)d_in[20];
    float* out = (float*)d_out;

    float *bufA = nullptr, *bufB = nullptr;
    cudaGetSymbolAddress((void**)&bufA, g_bufA);
    cudaGetSymbolAddress((void**)&bufB, g_bufB);

    build_csr<<<1, 1>>>(ei);

    // Layer 1: x[77824,256] @ W1[256,512] -> bufA ; agg -> bufB
    sgemm128<<<dim3(HH / 128, MM / 128), 256>>>(x, W1, bufA, MM, HH, FF);
    gat_agg<HH, true, false><<<BB, HH>>>(bufA, ei, as1, ad1, b1, bufB, nullptr, nullptr);

    // Layer 2
    sgemm128<<<dim3(HH / 128, MM / 128), 256>>>(bufB, W2, bufA, MM, HH, HH);
    gat_agg<HH, true, false><<<BB, HH>>>(bufA, ei, as2, ad2, b2, bufB, nullptr, nullptr);

    // Layer 3
    sgemm128<<<dim3(HH / 128, MM / 128), 256>>>(bufB, W3, bufA, MM, HH, HH);
    gat_agg<HH, true, false><<<BB, HH>>>(bufA, ei, as3, ad3, b3, bufB, nullptr, nullptr);

    // Layer 4 (C=256, no relu) + fused head -> d_out
    sgemm128<<<dim3(OO / 128, MM / 128), 256>>>(bufB, W4, bufA, MM, OO, HH);
    gat_agg<OO, false, true><<<BB, OO>>>(bufA, ei, as4, ad4, b4, out, ws, bs);
}

// round 3
// speedup vs baseline: 2.4475x; 2.4475x over previous
#include <cuda_runtime.h>
#include <cuda_bf16.h>
#include <stdint.h>
#include <math.h>

// ---------------------------------------------------------------------------
// Problem constants
// ---------------------------------------------------------------------------
#define BB 4096
#define NN 19
#define EE 342
#define ET 361
#define FF 256
#define HH 512
#define OO 256
#define MM (BB * NN)      // 77824, divisible by 128

// ---------------------------------------------------------------------------
// Scratch (device globals)
// ---------------------------------------------------------------------------
__device__ __nv_bfloat16 g_Ahi[(size_t)MM * HH];
__device__ __nv_bfloat16 g_Alo[(size_t)MM * HH];
__device__ float         g_H  [(size_t)MM * HH];
__device__ __nv_bfloat16 g_Wh[4][HH * HH];   // transposed weight splits [N,K]
__device__ __nv_bfloat16 g_Wl[4][HH * HH];

// ---------------------------------------------------------------------------
// Helpers
// ---------------------------------------------------------------------------
__device__ __forceinline__ uint32_t smem_u32(const void* p) {
    uint32_t a;
    asm("{ .reg .u64 t; cvta.to.shared.u64 t, %1; cvt.u32.u64 %0, t; }"
        : "=r"(a) : "l"(p));
    return a;
}
#define SWZ(o) ((o) ^ (((o) >> 3) & 0x70))

__device__ __forceinline__ void cp16(uint32_t s, const void* g) {
    asm volatile("cp.async.cg.shared.global [%0], [%1], 16;" :: "r"(s), "l"(g));
}

// ---------------------------------------------------------------------------
// Split kernels: fp32 -> (bf16 hi, bf16 lo)
// ---------------------------------------------------------------------------
__global__ void split_x_kernel(const float* __restrict__ x,
                               __nv_bfloat16* __restrict__ hi,
                               __nv_bfloat16* __restrict__ lo, size_t n) {
    size_t i = (size_t)blockIdx.x * 256 + threadIdx.x;
    if (i < n) {
        float v = x[i];
        __nv_bfloat16 h = __float2bfloat16(v);
        hi[i] = h;
        lo[i] = __float2bfloat16(v - __bfloat162float(h));
    }
}

// W [K,N] fp32 -> transposed splits [N,K] bf16
__global__ void split_w_kernel(const float* __restrict__ W,
                               __nv_bfloat16* __restrict__ hi,
                               __nv_bfloat16* __restrict__ lo, int K, int N) {
    int i = blockIdx.x * 256 + threadIdx.x;
    if (i < K * N) {
        int n = i / K, k = i % K;
        float v = W[(size_t)k * N + n];
        __nv_bfloat16 h = __float2bfloat16(v);
        hi[i] = h;
        lo[i] = __float2bfloat16(v - __bfloat162float(h));
    }
}

// ---------------------------------------------------------------------------
// mma.sync bf16x3 GEMM:  H[M, NT] = Afp32[M,K] @ Wfp32[K,NT]
//   3 accumulation passes: Ah*Bh + Al*Bh + Ah*Bl (fp32 accumulators).
// A: [M,K] bf16 row-major.  B: [NT,K] bf16 (N-major, K contiguous).
// CTA tile 128x128, 8 warps (4x2), warp tile 32x64.
// K-chunks of 64 (128B rows, XOR-swizzled), 3-stage cp.async pipeline.
// ---------------------------------------------------------------------------
#define GEMM_SMEM (3 * 32768)

template <int K, int NT>
__global__ void __launch_bounds__(256, 1)
gemm_mma(const __nv_bfloat16* __restrict__ Ahi, const __nv_bfloat16* __restrict__ Alo,
         const __nv_bfloat16* __restrict__ Bhi, const __nv_bfloat16* __restrict__ Blo,
         float* __restrict__ Hout)
{
    extern __shared__ char smem[];
    const uint32_t sb = smem_u32(smem);
    const int tid  = threadIdx.x;
    const int wid  = tid >> 5;
    const int lane = tid & 31;
    const int bm = blockIdx.y * 128;
    const int bn = blockIdx.x * 128;
    const int wm = wid & 3;        // 0..3  (M groups of 32)
    const int wn = wid >> 2;       // 0..1  (N halves of 64)

    constexpr int KC  = K / 64;
    constexpr int NCH = 3 * KC;

    const __nv_bfloat16* Aps[3] = { Ahi, Alo, Ahi };
    const __nv_bfloat16* Bps[3] = { Bhi, Bhi, Blo };

    auto issue = [&](int ch) {
        const int slot = ch % 3;
        const int pass = ch / KC;
        const int kb   = (ch - pass * KC) * 64;
        const __nv_bfloat16* Ap = Aps[pass];
        const __nv_bfloat16* Bp = Bps[pass];
        const uint32_t sa = sb + (uint32_t)slot * 32768u;
        const uint32_t sB = sa + 16384u;
        const int r = tid >> 3, c = tid & 7;   // 32 rows per i-step
#pragma unroll
        for (int i = 0; i < 4; i++) {
            int rr = r + i * 32;
            cp16(sa + SWZ((uint32_t)(rr * 128 + c * 16)),
                 Ap + (size_t)(bm + rr) * K + kb + c * 8);
        }
#pragma unroll
        for (int i = 0; i < 4; i++) {
            int rr = r + i * 32;
            cp16(sB + SWZ((uint32_t)(rr * 128 + c * 16)),
                 Bp + (size_t)(bn + rr) * K + kb + c * 8);
        }
    };

    float acc[2][8][4] = {};

    issue(0);
    asm volatile("cp.async.commit_group;" ::: "memory");
    issue(1);
    asm volatile("cp.async.commit_group;" ::: "memory");

    for (int ch = 0; ch < NCH; ch++) {
        asm volatile("cp.async.wait_group 1;" ::: "memory");
        __syncthreads();
        if (ch + 2 < NCH) issue(ch + 2);
        asm volatile("cp.async.commit_group;" ::: "memory");

        const uint32_t sa = sb + (uint32_t)(ch % 3) * 32768u;
        const uint32_t sB = sa + 16384u;
#pragma unroll
        for (int kk = 0; kk < 4; kk++) {
            // B fragments: 8 n8-tiles -> 16 regs, via 4 ldmatrix.x4
            uint32_t b[16];
#pragma unroll
            for (int g = 0; g < 4; g++) {
                int n = wn * 64 + g * 16 + ((lane >> 4) * 8) + (lane & 7);
                int c = kk * 2 + ((lane >> 3) & 1);
                uint32_t addr = sB + SWZ((uint32_t)(n * 128 + c * 16));
                asm volatile(
                    "ldmatrix.sync.aligned.m8n8.x4.shared.b16 {%0,%1,%2,%3}, [%4];"
                    : "=r"(b[g * 4 + 0]), "=r"(b[g * 4 + 1]),
                      "=r"(b[g * 4 + 2]), "=r"(b[g * 4 + 3])
                    : "r"(addr));
            }
#pragma unroll
            for (int mt = 0; mt < 2; mt++) {
                uint32_t a[4];
                int m = wm * 32 + mt * 16 + (lane & 15);
                int c = kk * 2 + (lane >> 4);
                uint32_t addr = sa + SWZ((uint32_t)(m * 128 + c * 16));
                asm volatile(
                    "ldmatrix.sync.aligned.m8n8.x4.shared.b16 {%0,%1,%2,%3}, [%4];"
                    : "=r"(a[0]), "=r"(a[1]), "=r"(a[2]), "=r"(a[3])
                    : "r"(addr));
#pragma unroll
                for (int nt = 0; nt < 8; nt++) {
                    float* d = acc[mt][nt];
                    asm volatile(
                        "mma.sync.aligned.m16n8k16.row.col.f32.bf16.bf16.f32 "
                        "{%0,%1,%2,%3}, {%4,%5,%6,%7}, {%8,%9}, {%0,%1,%2,%3};"
                        : "+f"(d[0]), "+f"(d[1]), "+f"(d[2]), "+f"(d[3])
                        : "r"(a[0]), "r"(a[1]), "r"(a[2]), "r"(a[3]),
                          "r"(b[nt * 2]), "r"(b[nt * 2 + 1]));
                }
            }
        }
    }

    // Epilogue: fp32 stores.  m16n8 acc layout: d0,d1 -> row (lane>>2),
    // cols (lane&3)*2+{0,1}; d2,d3 -> row+8.
#pragma unroll
    for (int mt = 0; mt < 2; mt++) {
        int row0 = bm + wm * 32 + mt * 16 + (lane >> 2);
#pragma unroll
        for (int nt = 0; nt < 8; nt++) {
            int col = bn + wn * 64 + nt * 8 + (lane & 3) * 2;
            *(float2*)(Hout + (size_t)row0 * NT + col) =
                make_float2(acc[mt][nt][0], acc[mt][nt][1]);
            *(float2*)(Hout + (size_t)(row0 + 8) * NT + col) =
                make_float2(acc[mt][nt][2], acc[mt][nt][3]);
        }
    }
}

// ---------------------------------------------------------------------------
// Attention + aggregation, dense-alpha. One CTA per graph, C threads.
// ---------------------------------------------------------------------------
__device__ __forceinline__ void atomicMaxF(float* addr, float v) {
    int* ai = (int*)addr;
    int old = __float_as_int(*addr);
    while (__int_as_float(old) < v) {
        int prev = atomicCAS(ai, old, __float_as_int(v));
        if (prev == old) break;
        old = prev;
    }
}

template <int C>
__device__ __forceinline__ void attn_alpha(
    const float* __restrict__ hs, const int* __restrict__ ei,
    const float* __restrict__ a_s, const float* __restrict__ a_d,
    float* als, float* ald, float* nmax, float* nsum, float* ebuf, float* alphaM,
    int t)
{
    // per-node logits
    {
        const int w = t >> 5, lane = t & 31, NW = C / 32;
        for (int n = w; n < NN; n += NW) {
            float s = 0.f, d = 0.f;
#pragma unroll
            for (int j = 0; j < C / 32; j++) {
                float h = hs[n * C + lane + 32 * j];
                s += h * __ldg(a_s + lane + 32 * j);
                d += h * __ldg(a_d + lane + 32 * j);
            }
#pragma unroll
            for (int o = 16; o; o >>= 1) {
                s += __shfl_xor_sync(0xffffffffu, s, o);
                d += __shfl_xor_sync(0xffffffffu, d, o);
            }
            if (lane == 0) { als[n] = s; ald[n] = d; }
        }
    }
    __syncthreads();
    for (int e = t; e < ET; e += C) {
        int se = (e < EE) ? ei[e] : (e - EE);
        int de = (e < EE) ? ei[EE + e] : (e - EE);
        float z = als[se] + ald[de];
        float lg = (z >= 0.f) ? z : 0.2f * z;
        ebuf[e] = lg;
        atomicMaxF(&nmax[de], lg);
    }
    __syncthreads();
    for (int e = t; e < ET; e += C) {
        int de = (e < EE) ? ei[EE + e] : (e - EE);
        float ex = expf(ebuf[e] - nmax[de]);
        ebuf[e] = ex;
        atomicAdd(&nsum[de], ex);
    }
    __syncthreads();
    for (int e = t; e < ET; e += C) {
        int se = (e < EE) ? ei[e] : (e - EE);
        int de = (e < EE) ? ei[EE + e] : (e - EE);
        atomicAdd(&alphaM[de * NN + se], ebuf[e] / nsum[de]);
    }
    __syncthreads();
}

template <int C, bool RELU>
__global__ void __launch_bounds__(C) gat_agg_bf(
    const float* __restrict__ H, const int* __restrict__ ei,
    const float* __restrict__ a_s, const float* __restrict__ a_d,
    const float* __restrict__ bias,
    __nv_bfloat16* __restrict__ Ohi, __nv_bfloat16* __restrict__ Olo)
{
    __shared__ alignas(16) float hs[NN * C];
    __shared__ float als[NN], ald[NN], nmax[NN], nsum[NN];
    __shared__ float ebuf[ET];
    __shared__ float alphaM[NN * NN];

    const int t = threadIdx.x;
    const size_t gbase = (size_t)blockIdx.x * NN * C;

    if (t < NN) { nmax[t] = -1e30f; nsum[t] = 0.f; }
    for (int i = t; i < NN * NN; i += C) alphaM[i] = 0.f;
    {
        const float4* H4 = (const float4*)(H + gbase);
        float4* hs4 = (float4*)hs;
        for (int i = t; i < NN * C / 4; i += C) hs4[i] = H4[i];
    }
    __syncthreads();

    attn_alpha<C>(hs, ei, a_s, a_d, als, ald, nmax, nsum, ebuf, alphaM, t);

    float hreg[NN];
#pragma unroll
    for (int s = 0; s < NN; s++) hreg[s] = hs[s * C + t];
    const float bc = bias[t];
#pragma unroll
    for (int n = 0; n < NN; n++) {
        float acc = 0.f;
#pragma unroll
        for (int s = 0; s < NN; s++) acc += alphaM[n * NN + s] * hreg[s];
        float v = acc + bc;
        if (RELU) v = fmaxf(v, 0.f);
        __nv_bfloat16 hi = __float2bfloat16(v);
        Ohi[gbase + (size_t)n * C + t] = hi;
        Olo[gbase + (size_t)n * C + t] = __float2bfloat16(v - __bfloat162float(hi));
    }
}

// Final layer: aggregation (no relu) + fused head
__global__ void __launch_bounds__(OO) gat_final(
    const float* __restrict__ H, const int* __restrict__ ei,
    const float* __restrict__ a_s, const float* __restrict__ a_d,
    const float* __restrict__ bias, float* __restrict__ outp,
    const float* __restrict__ ws, const float* __restrict__ bsc)
{
    constexpr int C = OO;
    __shared__ alignas(16) float hs[NN * C];
    __shared__ float als[NN], ald[NN], nmax[NN], nsum[NN];
    __shared__ float ebuf[ET];
    __shared__ float alphaM[NN * NN];
    __shared__ alignas(16) float outbuf[NN * C];
    __shared__ float pbuf[C];

    const int t = threadIdx.x;
    const size_t gbase = (size_t)blockIdx.x * NN * C;

    if (t < NN) { nmax[t] = -1e30f; nsum[t] = 0.f; }
    for (int i = t; i < NN * NN; i += C) alphaM[i] = 0.f;
    {
        const float4* H4 = (const float4*)(H + gbase);
        float4* hs4 = (float4*)hs;
        for (int i = t; i < NN * C / 4; i += C) hs4[i] = H4[i];
    }
    __syncthreads();

    attn_alpha<C>(hs, ei, a_s, a_d, als, ald, nmax, nsum, ebuf, alphaM, t);

    float hreg[NN];
#pragma unroll
    for (int s = 0; s < NN; s++) hreg[s] = hs[s * C + t];
    const float bc = bias[t];
#pragma unroll
    for (int n = 0; n < NN; n++) {
        float acc = 0.f;
#pragma unroll
        for (int s = 0; s < NN; s++) acc += alphaM[n * NN + s] * hreg[s];
        outbuf[n * C + t] = acc + bc;
    }
    __syncthreads();

    {
        float pv = 0.f;
#pragma unroll
        for (int n = 0; n < NN; n++) pv += ws[n] * outbuf[n * C + t];
        pbuf[t] = pv;
    }
    __syncthreads();
    {
        const int w = t >> 5, lane = t & 31, NW = C / 32;
        const float bv = bsc[0];
        for (int n = w; n < NN; n += NW) {
            float s = 0.f;
#pragma unroll
            for (int j = 0; j < C / 32; j++)
                s += outbuf[n * C + lane + 32 * j] * pbuf[lane + 32 * j];
#pragma unroll
            for (int o = 16; o; o >>= 1)
                s += __shfl_xor_sync(0xffffffffu, s, o);
            if (lane == 0)
                outp[(size_t)blockIdx.x * NN + n] = 1.f / (1.f + expf(-(s + bv)));
        }
    }
}

// ---------------------------------------------------------------------------
// Launch
// ---------------------------------------------------------------------------
extern "C" void kernel_launch(void* const* d_in, const int* in_sizes, int n_in,
                              void* d_out, int out_size)
{
    (void)in_sizes; (void)n_in; (void)out_size;
    const float* x   = (const float*)d_in[0];
    const int*   ei  = (const int*)  d_in[1];
    const float* W1  = (const float*)d_in[3];
    const float* as1 = (const float*)d_in[4];
    const float* ad1 = (const float*)d_in[5];
    const float* b1  = (const float*)d_in[6];
    const float* W2  = (const float*)d_in[7];
    const float* as2 = (const float*)d_in[8];
    const float* ad2 = (const float*)d_in[9];
    const float* b2  = (const float*)d_in[10];
    const float* W3  = (const float*)d_in[11];
    const float* as3 = (const float*)d_in[12];
    const float* ad3 = (const float*)d_in[13];
    const float* b3  = (const float*)d_in[14];
    const float* W4  = (const float*)d_in[15];
    const float* as4 = (const float*)d_in[16];
    const float* ad4 = (const float*)d_in[17];
    const float* b4  = (const float*)d_in[18];
    const float* ws  = (const float*)d_in[19];
    const float* bs  = (const float*)d_in[20];
    float* out = (float*)d_out;

    __nv_bfloat16 *Ahi, *Alo, *Wh, *Wl;
    float* Hb;
    cudaGetSymbolAddress((void**)&Ahi, g_Ahi);
    cudaGetSymbolAddress((void**)&Alo, g_Alo);
    cudaGetSymbolAddress((void**)&Hb,  g_H);
    cudaGetSymbolAddress((void**)&Wh,  g_Wh);
    cudaGetSymbolAddress((void**)&Wl,  g_Wl);

    cudaFuncSetAttribute(gemm_mma<FF, HH>, cudaFuncAttributeMaxDynamicSharedMemorySize, GEMM_SMEM);
    cudaFuncSetAttribute(gemm_mma<HH, HH>, cudaFuncAttributeMaxDynamicSharedMemorySize, GEMM_SMEM);
    cudaFuncSetAttribute(gemm_mma<HH, OO>, cudaFuncAttributeMaxDynamicSharedMemorySize, GEMM_SMEM);

    __nv_bfloat16* Wh0 = Wh + 0 * (HH * HH);
    __nv_bfloat16* Wh1 = Wh + 1 * (HH * HH);
    __nv_bfloat16* Wh2 = Wh + 2 * (HH * HH);
    __nv_bfloat16* Wh3 = Wh + 3 * (HH * HH);
    __nv_bfloat16* Wl0 = Wl + 0 * (HH * HH);
    __nv_bfloat16* Wl1 = Wl + 1 * (HH * HH);
    __nv_bfloat16* Wl2 = Wl + 2 * (HH * HH);
    __nv_bfloat16* Wl3 = Wl + 3 * (HH * HH);

    split_x_kernel<<<(MM * FF + 255) / 256, 256>>>(x, Ahi, Alo, (size_t)MM * FF);
    split_w_kernel<<<(FF * HH + 255) / 256, 256>>>(W1, Wh0, Wl0, FF, HH);
    split_w_kernel<<<(HH * HH + 255) / 256, 256>>>(W2, Wh1, Wl1, HH, HH);
    split_w_kernel<<<(HH * HH + 255) / 256, 256>>>(W3, Wh2, Wl2, HH, HH);
    split_w_kernel<<<(HH * OO + 255) / 256, 256>>>(W4, Wh3, Wl3, HH, OO);

    const dim3 g2(HH / 128, MM / 128);   // (4, 608)
    const dim3 g1(OO / 128, MM / 128);   // (2, 608)

    // Layer 1
    gemm_mma<FF, HH><<<g2, 256, GEMM_SMEM>>>(Ahi, Alo, Wh0, Wl0, Hb);
    gat_agg_bf<HH, true><<<BB, HH>>>(Hb, ei, as1, ad1, b1, Ahi, Alo);
    // Layer 2
    gemm_mma<HH, HH><<<g2, 256, GEMM_SMEM>>>(Ahi, Alo, Wh1, Wl1, Hb);
    gat_agg_bf<HH, true><<<BB, HH>>>(Hb, ei, as2, ad2, b2, Ahi, Alo);
    // Layer 3
    gemm_mma<HH, HH><<<g2, 256, GEMM_SMEM>>>(Ahi, Alo, Wh2, Wl2, Hb);
    gat_agg_bf<HH, true><<<BB, HH>>>(Hb, ei, as3, ad3, b3, Ahi, Alo);
    // Layer 4 + fused head
    gemm_mma<HH, OO><<<g1, 256, GEMM_SMEM>>>(Ahi, Alo, Wh3, Wl3, Hb);
    gat_final<<<BB, OO>>>(Hb, ei, as4, ad4, b4, out, ws, bs);
}

// round 4
// speedup vs baseline: 2.7266x; 1.1140x over previous
#include <cuda_runtime.h>
#include <cuda_bf16.h>
#include <stdint.h>
#include <math.h>

// ---------------------------------------------------------------------------
// Problem constants
// ---------------------------------------------------------------------------
#define BB 4096
#define NN 19
#define EE 342
#define ET 361
#define FF 256
#define HH 512
#define OO 256
#define MM (BB * NN)      // 77824, divisible by 128

// ---------------------------------------------------------------------------
// Scratch (device globals)
// ---------------------------------------------------------------------------
__device__ __nv_bfloat16 g_Ahi[(size_t)MM * HH];
__device__ __nv_bfloat16 g_Alo[(size_t)MM * HH];
__device__ float         g_H  [(size_t)MM * HH];
__device__ __nv_bfloat16 g_Wh[4][HH * HH];   // transposed weight splits [N,K]
__device__ __nv_bfloat16 g_Wl[4][HH * HH];

// ---------------------------------------------------------------------------
// Helpers
// ---------------------------------------------------------------------------
__device__ __forceinline__ uint32_t smem_u32(const void* p) {
    uint32_t a;
    asm("{ .reg .u64 t; cvta.to.shared.u64 t, %1; cvt.u32.u64 %0, t; }"
        : "=r"(a) : "l"(p));
    return a;
}
#define SWZ(o) ((o) ^ (((o) >> 3) & 0x70))

__device__ __forceinline__ void cp16(uint32_t s, const void* g) {
    asm volatile("cp.async.cg.shared.global [%0], [%1], 16;" :: "r"(s), "l"(g));
}

// ---------------------------------------------------------------------------
// Split kernels: fp32 -> (bf16 hi, bf16 lo)
// ---------------------------------------------------------------------------
__global__ void split_x_kernel(const float* __restrict__ x,
                               __nv_bfloat16* __restrict__ hi,
                               __nv_bfloat16* __restrict__ lo, size_t n) {
    size_t i = (size_t)blockIdx.x * 256 + threadIdx.x;
    if (i < n) {
        float v = x[i];
        __nv_bfloat16 h = __float2bfloat16(v);
        hi[i] = h;
        lo[i] = __float2bfloat16(v - __bfloat162float(h));
    }
}

// W [K,N] fp32 -> transposed splits [N,K] bf16
__global__ void split_w_kernel(const float* __restrict__ W,
                               __nv_bfloat16* __restrict__ hi,
                               __nv_bfloat16* __restrict__ lo, int K, int N) {
    int i = blockIdx.x * 256 + threadIdx.x;
    if (i < K * N) {
        int n = i / K, k = i % K;
        float v = W[(size_t)k * N + n];
        __nv_bfloat16 h = __float2bfloat16(v);
        hi[i] = h;
        lo[i] = __float2bfloat16(v - __bfloat162float(h));
    }
}

// ---------------------------------------------------------------------------
// mma.sync bf16x3 GEMM:  H[M, NT] = Afp32[M,K] @ Wfp32[K,NT]
//   3 accumulation passes: Ah*Bh + Al*Bh + Ah*Bl (fp32 accumulators).
// A: [M,K] bf16 row-major.  B: [NT,K] bf16 (N-major, K contiguous).
// CTA tile 128x256, 8 warps (2Mx4N), warp tile 64x64.
// K-chunks of 64 (128B rows, XOR-swizzled), 4-stage cp.async pipeline.
// ---------------------------------------------------------------------------
#define GEMM_STAGE 49152
#define GEMM_SMEM  (4 * GEMM_STAGE)

template <int K, int NT>
__global__ void __launch_bounds__(256, 1)
gemm_mma(const __nv_bfloat16* __restrict__ Ahi, const __nv_bfloat16* __restrict__ Alo,
         const __nv_bfloat16* __restrict__ Bhi, const __nv_bfloat16* __restrict__ Blo,
         float* __restrict__ Hout)
{
    extern __shared__ char smem[];
    const uint32_t sb = smem_u32(smem);
    const int tid  = threadIdx.x;
    const int wid  = tid >> 5;
    const int lane = tid & 31;
    const int bm = blockIdx.y * 128;
    const int bn = blockIdx.x * 256;
    const int wm = wid & 1;        // 0..1  (M halves of 64)
    const int wn = wid >> 1;       // 0..3  (N quarters of 64)

    constexpr int KC  = K / 64;
    constexpr int NCH = 3 * KC;

    const __nv_bfloat16* Aps[3] = { Ahi, Alo, Ahi };
    const __nv_bfloat16* Bps[3] = { Bhi, Bhi, Blo };

    auto issue = [&](int ch) {
        const int slot = ch & 3;
        const int pass = ch / KC;
        const int kb   = (ch - pass * KC) * 64;
        const __nv_bfloat16* Ap = Aps[pass];
        const __nv_bfloat16* Bp = Bps[pass];
        const uint32_t sa = sb + (uint32_t)slot * GEMM_STAGE;
        const uint32_t sB = sa + 16384u;
        const int r = tid >> 3, c = tid & 7;   // 32 rows per i-step
#pragma unroll
        for (int i = 0; i < 4; i++) {          // A: 128 rows
            int rr = r + i * 32;
            cp16(sa + SWZ((uint32_t)(rr * 128 + c * 16)),
                 Ap + (size_t)(bm + rr) * K + kb + c * 8);
        }
#pragma unroll
        for (int i = 0; i < 8; i++) {          // B: 256 rows
            int rr = r + i * 32;
            cp16(sB + SWZ((uint32_t)(rr * 128 + c * 16)),
                 Bp + (size_t)(bn + rr) * K + kb + c * 8);
        }
    };

    float acc[4][8][4] = {};

    issue(0);
    asm volatile("cp.async.commit_group;" ::: "memory");
    issue(1);
    asm volatile("cp.async.commit_group;" ::: "memory");
    issue(2);
    asm volatile("cp.async.commit_group;" ::: "memory");

    for (int ch = 0; ch < NCH; ch++) {
        asm volatile("cp.async.wait_group 2;" ::: "memory");
        __syncthreads();
        if (ch + 3 < NCH) issue(ch + 3);
        asm volatile("cp.async.commit_group;" ::: "memory");

        const uint32_t sa = sb + (uint32_t)(ch & 3) * GEMM_STAGE;
        const uint32_t sB = sa + 16384u;
#pragma unroll
        for (int kk = 0; kk < 4; kk++) {
            // B fragments: warp's 64 cols -> 8 n8-tiles -> 16 regs
            uint32_t b[16];
#pragma unroll
            for (int g = 0; g < 4; g++) {
                int n = wn * 64 + g * 16 + ((lane >> 4) * 8) + (lane & 7);
                int c = kk * 2 + ((lane >> 3) & 1);
                uint32_t addr = sB + SWZ((uint32_t)(n * 128 + c * 16));
                asm volatile(
                    "ldmatrix.sync.aligned.m8n8.x4.shared.b16 {%0,%1,%2,%3}, [%4];"
                    : "=r"(b[g * 4 + 0]), "=r"(b[g * 4 + 1]),
                      "=r"(b[g * 4 + 2]), "=r"(b[g * 4 + 3])
                    : "r"(addr));
            }
#pragma unroll
            for (int mt = 0; mt < 4; mt++) {
                uint32_t a[4];
                int m = wm * 64 + mt * 16 + (lane & 15);
                int c = kk * 2 + (lane >> 4);
                uint32_t addr = sa + SWZ((uint32_t)(m * 128 + c * 16));
                asm volatile(
                    "ldmatrix.sync.aligned.m8n8.x4.shared.b16 {%0,%1,%2,%3}, [%4];"
                    : "=r"(a[0]), "=r"(a[1]), "=r"(a[2]), "=r"(a[3])
                    : "r"(addr));
#pragma unroll
                for (int nt = 0; nt < 8; nt++) {
                    float* d = acc[mt][nt];
                    asm volatile(
                        "mma.sync.aligned.m16n8k16.row.col.f32.bf16.bf16.f32 "
                        "{%0,%1,%2,%3}, {%4,%5,%6,%7}, {%8,%9}, {%0,%1,%2,%3};"
                        : "+f"(d[0]), "+f"(d[1]), "+f"(d[2]), "+f"(d[3])
                        : "r"(a[0]), "r"(a[1]), "r"(a[2]), "r"(a[3]),
                          "r"(b[nt * 2]), "r"(b[nt * 2 + 1]));
                }
            }
        }
    }

    // Epilogue: fp32 stores.
#pragma unroll
    for (int mt = 0; mt < 4; mt++) {
        int row0 = bm + wm * 64 + mt * 16 + (lane >> 2);
#pragma unroll
        for (int nt = 0; nt < 8; nt++) {
            int col = bn + wn * 64 + nt * 8 + (lane & 3) * 2;
            *(float2*)(Hout + (size_t)row0 * NT + col) =
                make_float2(acc[mt][nt][0], acc[mt][nt][1]);
            *(float2*)(Hout + (size_t)(row0 + 8) * NT + col) =
                make_float2(acc[mt][nt][2], acc[mt][nt][3]);
        }
    }
}

// ---------------------------------------------------------------------------
// Attention + aggregation, dense-alpha. One CTA per graph, C threads.
// ---------------------------------------------------------------------------
__device__ __forceinline__ void atomicMaxF(float* addr, float v) {
    int* ai = (int*)addr;
    int old = __float_as_int(*addr);
    while (__int_as_float(old) < v) {
        int prev = atomicCAS(ai, old, __float_as_int(v));
        if (prev == old) break;
        old = prev;
    }
}

template <int C>
__device__ __forceinline__ void attn_alpha(
    const float* __restrict__ hs, const int* __restrict__ ei,
    const float* __restrict__ a_s, const float* __restrict__ a_d,
    float* als, float* ald, float* nmax, float* nsum, float* ebuf, float* alphaM,
    int t)
{
    // per-node logits
    {
        const int w = t >> 5, lane = t & 31, NW = C / 32;
        for (int n = w; n < NN; n += NW) {
            float s = 0.f, d = 0.f;
#pragma unroll
            for (int j = 0; j < C / 32; j++) {
                float h = hs[n * C + lane + 32 * j];
                s += h * __ldg(a_s + lane + 32 * j);
                d += h * __ldg(a_d + lane + 32 * j);
            }
#pragma unroll
            for (int o = 16; o; o >>= 1) {
                s += __shfl_xor_sync(0xffffffffu, s, o);
                d += __shfl_xor_sync(0xffffffffu, d, o);
            }
            if (lane == 0) { als[n] = s; ald[n] = d; }
        }
    }
    __syncthreads();
    for (int e = t; e < ET; e += C) {
        int se = (e < EE) ? ei[e] : (e - EE);
        int de = (e < EE) ? ei[EE + e] : (e - EE);
        float z = als[se] + ald[de];
        float lg = (z >= 0.f) ? z : 0.2f * z;
        ebuf[e] = lg;
        atomicMaxF(&nmax[de], lg);
    }
    __syncthreads();
    for (int e = t; e < ET; e += C) {
        int de = (e < EE) ? ei[EE + e] : (e - EE);
        float ex = __expf(ebuf[e] - nmax[de]);
        ebuf[e] = ex;
        atomicAdd(&nsum[de], ex);
    }
    __syncthreads();
    if (t < NN) nsum[t] = 1.f / nsum[t];
    __syncthreads();
    for (int e = t; e < ET; e += C) {
        int se = (e < EE) ? ei[e] : (e - EE);
        int de = (e < EE) ? ei[EE + e] : (e - EE);
        atomicAdd(&alphaM[de * NN + se], ebuf[e] * nsum[de]);
    }
    __syncthreads();
}

template <int C, bool RELU>
__global__ void __launch_bounds__(C) gat_agg_bf(
    const float* __restrict__ H, const int* __restrict__ ei,
    const float* __restrict__ a_s, const float* __restrict__ a_d,
    const float* __restrict__ bias,
    __nv_bfloat16* __restrict__ Ohi, __nv_bfloat16* __restrict__ Olo)
{
    __shared__ alignas(16) float hs[NN * C];
    __shared__ float als[NN], ald[NN], nmax[NN], nsum[NN];
    __shared__ float ebuf[ET];
    __shared__ float alphaM[NN * NN];

    const int t = threadIdx.x;
    const size_t gbase = (size_t)blockIdx.x * NN * C;

    if (t < NN) { nmax[t] = -1e30f; nsum[t] = 0.f; }
    for (int i = t; i < NN * NN; i += C) alphaM[i] = 0.f;
    {
        const float4* H4 = (const float4*)(H + gbase);
        float4* hs4 = (float4*)hs;
        for (int i = t; i < NN * C / 4; i += C) hs4[i] = H4[i];
    }
    __syncthreads();

    attn_alpha<C>(hs, ei, a_s, a_d, als, ald, nmax, nsum, ebuf, alphaM, t);

    float hreg[NN];
#pragma unroll
    for (int s = 0; s < NN; s++) hreg[s] = hs[s * C + t];
    const float bc = bias[t];
#pragma unroll
    for (int n = 0; n < NN; n++) {
        float acc = 0.f;
#pragma unroll
        for (int s = 0; s < NN; s++) acc += alphaM[n * NN + s] * hreg[s];
        float v = acc + bc;
        if (RELU) v = fmaxf(v, 0.f);
        __nv_bfloat16 hi = __float2bfloat16(v);
        Ohi[gbase + (size_t)n * C + t] = hi;
        Olo[gbase + (size_t)n * C + t] = __float2bfloat16(v - __bfloat162float(hi));
    }
}

// Final layer: aggregation (no relu) + fused head
__global__ void __launch_bounds__(OO) gat_final(
    const float* __restrict__ H, const int* __restrict__ ei,
    const float* __restrict__ a_s, const float* __restrict__ a_d,
    const float* __restrict__ bias, float* __restrict__ outp,
    const float* __restrict__ ws, const float* __restrict__ bsc)
{
    constexpr int C = OO;
    __shared__ alignas(16) float hs[NN * C];
    __shared__ float als[NN], ald[NN], nmax[NN], nsum[NN];
    __shared__ float ebuf[ET];
    __shared__ float alphaM[NN * NN];
    __shared__ alignas(16) float outbuf[NN * C];
    __shared__ float pbuf[C];

    const int t = threadIdx.x;
    const size_t gbase = (size_t)blockIdx.x * NN * C;

    if (t < NN) { nmax[t] = -1e30f; nsum[t] = 0.f; }
    for (int i = t; i < NN * NN; i += C) alphaM[i] = 0.f;
    {
        const float4* H4 = (const float4*)(H + gbase);
        float4* hs4 = (float4*)hs;
        for (int i = t; i < NN * C / 4; i += C) hs4[i] = H4[i];
    }
    __syncthreads();

    attn_alpha<C>(hs, ei, a_s, a_d, als, ald, nmax, nsum, ebuf, alphaM, t);

    float hreg[NN];
#pragma unroll
    for (int s = 0; s < NN; s++) hreg[s] = hs[s * C + t];
    const float bc = bias[t];
#pragma unroll
    for (int n = 0; n < NN; n++) {
        float acc = 0.f;
#pragma unroll
        for (int s = 0; s < NN; s++) acc += alphaM[n * NN + s] * hreg[s];
        outbuf[n * C + t] = acc + bc;
    }
    __syncthreads();

    {
        float pv = 0.f;
#pragma unroll
        for (int n = 0; n < NN; n++) pv += ws[n] * outbuf[n * C + t];
        pbuf[t] = pv;
    }
    __syncthreads();
    {
        const int w = t >> 5, lane = t & 31, NW = C / 32;
        const float bv = bsc[0];
        for (int n = w; n < NN; n += NW) {
            float s = 0.f;
#pragma unroll
            for (int j = 0; j < C / 32; j++)
                s += outbuf[n * C + lane + 32 * j] * pbuf[lane + 32 * j];
#pragma unroll
            for (int o = 16; o; o >>= 1)
                s += __shfl_xor_sync(0xffffffffu, s, o);
            if (lane == 0)
                outp[(size_t)blockIdx.x * NN + n] = 1.f / (1.f + __expf(-(s + bv)));
        }
    }
}

// ---------------------------------------------------------------------------
// Launch
// ---------------------------------------------------------------------------
extern "C" void kernel_launch(void* const* d_in, const int* in_sizes, int n_in,
                              void* d_out, int out_size)
{
    (void)in_sizes; (void)n_in; (void)out_size;
    const float* x   = (const float*)d_in[0];
    const int*   ei  = (const int*)  d_in[1];
    const float* W1  = (const float*)d_in[3];
    const float* as1 = (const float*)d_in[4];
    const float* ad1 = (const float*)d_in[5];
    const float* b1  = (const float*)d_in[6];
    const float* W2  = (const float*)d_in[7];
    const float* as2 = (const float*)d_in[8];
    const float* ad2 = (const float*)d_in[9];
    const float* b2  = (const float*)d_in[10];
    const float* W3  = (const float*)d_in[11];
    const float* as3 = (const float*)d_in[12];
    const float* ad3 = (const float*)d_in[13];
    const float* b3  = (const float*)d_in[14];
    const float* W4  = (const float*)d_in[15];
    const float* as4 = (const float*)d_in[16];
    const float* ad4 = (const float*)d_in[17];
    const float* b4  = (const float*)d_in[18];
    const float* ws  = (const float*)d_in[19];
    const float* bs  = (const float*)d_in[20];
    float* out = (float*)d_out;

    __nv_bfloat16 *Ahi, *Alo, *Wh, *Wl;
    float* Hb;
    cudaGetSymbolAddress((void**)&Ahi, g_Ahi);
    cudaGetSymbolAddress((void**)&Alo, g_Alo);
    cudaGetSymbolAddress((void**)&Hb,  g_H);
    cudaGetSymbolAddress((void**)&Wh,  g_Wh);
    cudaGetSymbolAddress((void**)&Wl,  g_Wl);

    cudaFuncSetAttribute(gemm_mma<FF, HH>, cudaFuncAttributeMaxDynamicSharedMemorySize, GEMM_SMEM);
    cudaFuncSetAttribute(gemm_mma<HH, HH>, cudaFuncAttributeMaxDynamicSharedMemorySize, GEMM_SMEM);
    cudaFuncSetAttribute(gemm_mma<HH, OO>, cudaFuncAttributeMaxDynamicSharedMemorySize, GEMM_SMEM);

    __nv_bfloat16* Wh0 = Wh + 0 * (HH * HH);
    __nv_bfloat16* Wh1 = Wh + 1 * (HH * HH);
    __nv_bfloat16* Wh2 = Wh + 2 * (HH * HH);
    __nv_bfloat16* Wh3 = Wh + 3 * (HH * HH);
    __nv_bfloat16* Wl0 = Wl + 0 * (HH * HH);
    __nv_bfloat16* Wl1 = Wl + 1 * (HH * HH);
    __nv_bfloat16* Wl2 = Wl + 2 * (HH * HH);
    __nv_bfloat16* Wl3 = Wl + 3 * (HH * HH);

    split_x_kernel<<<(MM * FF + 255) / 256, 256>>>(x, Ahi, Alo, (size_t)MM * FF);
    split_w_kernel<<<(FF * HH + 255) / 256, 256>>>(W1, Wh0, Wl0, FF, HH);
    split_w_kernel<<<(HH * HH + 255) / 256, 256>>>(W2, Wh1, Wl1, HH, HH);
    split_w_kernel<<<(HH * HH + 255) / 256, 256>>>(W3, Wh2, Wl2, HH, HH);
    split_w_kernel<<<(HH * OO + 255) / 256, 256>>>(W4, Wh3, Wl3, HH, OO);

    const dim3 g2(HH / 256, MM / 128);   // (2, 608)
    const dim3 g1(OO / 256, MM / 128);   // (1, 608)

    // Layer 1
    gemm_mma<FF, HH><<<g2, 256, GEMM_SMEM>>>(Ahi, Alo, Wh0, Wl0, Hb);
    gat_agg_bf<HH, true><<<BB, HH>>>(Hb, ei, as1, ad1, b1, Ahi, Alo);
    // Layer 2
    gemm_mma<HH, HH><<<g2, 256, GEMM_SMEM>>>(Ahi, Alo, Wh1, Wl1, Hb);
    gat_agg_bf<HH, true><<<BB, HH>>>(Hb, ei, as2, ad2, b2, Ahi, Alo);
    // Layer 3
    gemm_mma<HH, HH><<<g2, 256, GEMM_SMEM>>>(Ahi, Alo, Wh2, Wl2, Hb);
    gat_agg_bf<HH, true><<<BB, HH>>>(Hb, ei, as3, ad3, b3, Ahi, Alo);
    // Layer 4 + fused head
    gemm_mma<HH, OO><<<g1, 256, GEMM_SMEM>>>(Ahi, Alo, Wh3, Wl3, Hb);
    gat_final<<<BB, OO>>>(Hb, ei, as4, ad4, b4, out, ws, bs);
}

// round 5
// speedup vs baseline: 2.8600x; 1.0490x over previous
#include <cuda_runtime.h>
#include <cuda_bf16.h>
#include <stdint.h>
#include <math.h>

// ---------------------------------------------------------------------------
// Problem constants
// ---------------------------------------------------------------------------
#define BB 4096
#define NN 19
#define EE 342
#define ET 361
#define FF 256
#define HH 512
#define OO 256
#define MM (BB * NN)      // 77824, divisible by 128

// ---------------------------------------------------------------------------
// Scratch (device globals)
// ---------------------------------------------------------------------------
__device__ __nv_bfloat16 g_Ahi[(size_t)MM * HH];
__device__ __nv_bfloat16 g_Alo[(size_t)MM * HH];
__device__ float         g_H  [(size_t)MM * HH];
__device__ __nv_bfloat16 g_Wh[4][HH * HH];   // transposed weight splits [N,K]
__device__ __nv_bfloat16 g_Wl[4][HH * HH];

// ---------------------------------------------------------------------------
// Helpers
// ---------------------------------------------------------------------------
__device__ __forceinline__ uint32_t smem_u32(const void* p) {
    uint32_t a;
    asm("{ .reg .u64 t; cvta.to.shared.u64 t, %1; cvt.u32.u64 %0, t; }"
        : "=r"(a) : "l"(p));
    return a;
}
#define SWZ(o) ((o) ^ (((o) >> 3) & 0x70))

__device__ __forceinline__ void cp16(uint32_t s, const void* g) {
    asm volatile("cp.async.cg.shared.global [%0], [%1], 16;" :: "r"(s), "l"(g));
}

// ---------------------------------------------------------------------------
// Split kernels: fp32 -> (bf16 hi, bf16 lo)
// ---------------------------------------------------------------------------
__global__ void split_x_kernel(const float* __restrict__ x,
                               __nv_bfloat16* __restrict__ hi,
                               __nv_bfloat16* __restrict__ lo, size_t n) {
    size_t i = (size_t)blockIdx.x * 256 + threadIdx.x;
    if (i < n) {
        float v = x[i];
        __nv_bfloat16 h = __float2bfloat16(v);
        hi[i] = h;
        lo[i] = __float2bfloat16(v - __bfloat162float(h));
    }
}

// W [K,N] fp32 -> transposed splits [N,K] bf16
__global__ void split_w_kernel(const float* __restrict__ W,
                               __nv_bfloat16* __restrict__ hi,
                               __nv_bfloat16* __restrict__ lo, int K, int N) {
    int i = blockIdx.x * 256 + threadIdx.x;
    if (i < K * N) {
        int n = i / K, k = i % K;
        float v = W[(size_t)k * N + n];
        __nv_bfloat16 h = __float2bfloat16(v);
        hi[i] = h;
        lo[i] = __float2bfloat16(v - __bfloat162float(h));
    }
}

// ---------------------------------------------------------------------------
// mma.sync bf16x3 GEMM, pass-interleaved:
//   H[M,NT] = Ah*Bh + Al*Bh + Ah*Bl  (fp32 accumulators), all three products
//   issued per K-chunk from one load of (Ah, Al, Bh, Bl).
// A: [M,K] bf16 row-major.  B: [NT,K] bf16 (N-major, K contiguous).
// CTA tile 128x256, 8 warps (2Mx4N), warp tile 64x64.
// K-chunks of 64 (128B rows, XOR-swizzled), 2-stage cp.async pipeline,
// stage = Ah(16K) | Al(16K) | Bh(32K) | Bl(32K) = 96KB.
// ---------------------------------------------------------------------------
#define GEMM_STAGE 98304
#define GEMM_SMEM  (2 * GEMM_STAGE)

template <int K, int NT>
__global__ void __launch_bounds__(256, 1)
gemm_mma(const __nv_bfloat16* __restrict__ Ahi, const __nv_bfloat16* __restrict__ Alo,
         const __nv_bfloat16* __restrict__ Bhi, const __nv_bfloat16* __restrict__ Blo,
         float* __restrict__ Hout)
{
    extern __shared__ char smem[];
    const uint32_t sb = smem_u32(smem);
    const int tid  = threadIdx.x;
    const int wid  = tid >> 5;
    const int lane = tid & 31;
    const int bm = blockIdx.y * 128;
    const int bn = blockIdx.x * 256;
    const int wm = wid & 1;        // 0..1  (M halves of 64)
    const int wn = wid >> 1;       // 0..3  (N quarters of 64)

    constexpr int NCH = K / 64;    // K-chunks

    auto issue = [&](int ch) {
        const uint32_t st = sb + (uint32_t)(ch & 1) * GEMM_STAGE;
        const int kb = ch * 64;
        const int r = tid >> 3, c = tid & 7;   // 32 rows per i-step
#pragma unroll
        for (int i = 0; i < 4; i++) {          // A: 128 rows (hi + lo)
            int rr = r + i * 32;
            size_t go = (size_t)(bm + rr) * K + kb + c * 8;
            uint32_t so = SWZ((uint32_t)(rr * 128 + c * 16));
            cp16(st + so,          Ahi + go);
            cp16(st + 16384u + so, Alo + go);
        }
#pragma unroll
        for (int i = 0; i < 8; i++) {          // B: 256 rows (hi + lo)
            int rr = r + i * 32;
            size_t go = (size_t)(bn + rr) * K + kb + c * 8;
            uint32_t so = SWZ((uint32_t)(rr * 128 + c * 16));
            cp16(st + 32768u + so, Bhi + go);
            cp16(st + 65536u + so, Blo + go);
        }
    };

    float acc[4][8][4] = {};

    issue(0);
    asm volatile("cp.async.commit_group;" ::: "memory");

    for (int ch = 0; ch < NCH; ch++) {
        if (ch + 1 < NCH) {
            issue(ch + 1);
            asm volatile("cp.async.commit_group;" ::: "memory");
            asm volatile("cp.async.wait_group 1;" ::: "memory");
        } else {
            asm volatile("cp.async.wait_group 0;" ::: "memory");
        }
        __syncthreads();

        const uint32_t st  = sb + (uint32_t)(ch & 1) * GEMM_STAGE;
        const uint32_t sAh = st;
        const uint32_t sAl = st + 16384u;
        const uint32_t sBh = st + 32768u;
        const uint32_t sBl = st + 65536u;
#pragma unroll
        for (int kk = 0; kk < 4; kk++) {
            // B fragments (hi and lo): warp's 64 cols -> 8 n8-tiles -> 16 regs each
            uint32_t bh[16], bl[16];
#pragma unroll
            for (int g = 0; g < 4; g++) {
                int n = wn * 64 + g * 16 + ((lane >> 4) * 8) + (lane & 7);
                int c = kk * 2 + ((lane >> 3) & 1);
                uint32_t so = SWZ((uint32_t)(n * 128 + c * 16));
                asm volatile(
                    "ldmatrix.sync.aligned.m8n8.x4.shared.b16 {%0,%1,%2,%3}, [%4];"
                    : "=r"(bh[g * 4 + 0]), "=r"(bh[g * 4 + 1]),
                      "=r"(bh[g * 4 + 2]), "=r"(bh[g * 4 + 3])
                    : "r"(sBh + so));
                asm volatile(
                    "ldmatrix.sync.aligned.m8n8.x4.shared.b16 {%0,%1,%2,%3}, [%4];"
                    : "=r"(bl[g * 4 + 0]), "=r"(bl[g * 4 + 1]),
                      "=r"(bl[g * 4 + 2]), "=r"(bl[g * 4 + 3])
                    : "r"(sBl + so));
            }
#pragma unroll
            for (int mt = 0; mt < 4; mt++) {
                uint32_t ah[4], al[4];
                int m = wm * 64 + mt * 16 + (lane & 15);
                int c = kk * 2 + (lane >> 4);
                uint32_t so = SWZ((uint32_t)(m * 128 + c * 16));
                asm volatile(
                    "ldmatrix.sync.aligned.m8n8.x4.shared.b16 {%0,%1,%2,%3}, [%4];"
                    : "=r"(ah[0]), "=r"(ah[1]), "=r"(ah[2]), "=r"(ah[3])
                    : "r"(sAh + so));
                asm volatile(
                    "ldmatrix.sync.aligned.m8n8.x4.shared.b16 {%0,%1,%2,%3}, [%4];"
                    : "=r"(al[0]), "=r"(al[1]), "=r"(al[2]), "=r"(al[3])
                    : "r"(sAl + so));
#pragma unroll
                for (int nt = 0; nt < 8; nt++) {
                    float* d = acc[mt][nt];
                    asm volatile(
                        "mma.sync.aligned.m16n8k16.row.col.f32.bf16.bf16.f32 "
                        "{%0,%1,%2,%3}, {%4,%5,%6,%7}, {%8,%9}, {%0,%1,%2,%3};"
                        : "+f"(d[0]), "+f"(d[1]), "+f"(d[2]), "+f"(d[3])
                        : "r"(ah[0]), "r"(ah[1]), "r"(ah[2]), "r"(ah[3]),
                          "r"(bh[nt * 2]), "r"(bh[nt * 2 + 1]));
                    asm volatile(
                        "mma.sync.aligned.m16n8k16.row.col.f32.bf16.bf16.f32 "
                        "{%0,%1,%2,%3}, {%4,%5,%6,%7}, {%8,%9}, {%0,%1,%2,%3};"
                        : "+f"(d[0]), "+f"(d[1]), "+f"(d[2]), "+f"(d[3])
                        : "r"(al[0]), "r"(al[1]), "r"(al[2]), "r"(al[3]),
                          "r"(bh[nt * 2]), "r"(bh[nt * 2 + 1]));
                    asm volatile(
                        "mma.sync.aligned.m16n8k16.row.col.f32.bf16.bf16.f32 "
                        "{%0,%1,%2,%3}, {%4,%5,%6,%7}, {%8,%9}, {%0,%1,%2,%3};"
                        : "+f"(d[0]), "+f"(d[1]), "+f"(d[2]), "+f"(d[3])
                        : "r"(ah[0]), "r"(ah[1]), "r"(ah[2]), "r"(ah[3]),
                          "r"(bl[nt * 2]), "r"(bl[nt * 2 + 1]));
                }
            }
        }
        __syncthreads();
    }

    // Epilogue: fp32 stores.
#pragma unroll
    for (int mt = 0; mt < 4; mt++) {
        int row0 = bm + wm * 64 + mt * 16 + (lane >> 2);
#pragma unroll
        for (int nt = 0; nt < 8; nt++) {
            int col = bn + wn * 64 + nt * 8 + (lane & 3) * 2;
            *(float2*)(Hout + (size_t)row0 * NT + col) =
                make_float2(acc[mt][nt][0], acc[mt][nt][1]);
            *(float2*)(Hout + (size_t)(row0 + 8) * NT + col) =
                make_float2(acc[mt][nt][2], acc[mt][nt][3]);
        }
    }
}

// ---------------------------------------------------------------------------
// Attention + aggregation, dense-alpha. One CTA per graph, C threads.
// ---------------------------------------------------------------------------
__device__ __forceinline__ void atomicMaxF(float* addr, float v) {
    int* ai = (int*)addr;
    int old = __float_as_int(*addr);
    while (__int_as_float(old) < v) {
        int prev = atomicCAS(ai, old, __float_as_int(v));
        if (prev == old) break;
        old = prev;
    }
}

template <int C>
__device__ __forceinline__ void attn_alpha(
    const float* __restrict__ hs, const int* __restrict__ ei,
    const float* __restrict__ a_s, const float* __restrict__ a_d,
    float* als, float* ald, float* nmax, float* nsum, float* ebuf, float* alphaM,
    int t)
{
    // per-node logits
    {
        const int w = t >> 5, lane = t & 31, NW = C / 32;
        for (int n = w; n < NN; n += NW) {
            float s = 0.f, d = 0.f;
#pragma unroll
            for (int j = 0; j < C / 32; j++) {
                float h = hs[n * C + lane + 32 * j];
                s += h * __ldg(a_s + lane + 32 * j);
                d += h * __ldg(a_d + lane + 32 * j);
            }
#pragma unroll
            for (int o = 16; o; o >>= 1) {
                s += __shfl_xor_sync(0xffffffffu, s, o);
                d += __shfl_xor_sync(0xffffffffu, d, o);
            }
            if (lane == 0) { als[n] = s; ald[n] = d; }
        }
    }
    __syncthreads();
    for (int e = t; e < ET; e += C) {
        int se = (e < EE) ? ei[e] : (e - EE);
        int de = (e < EE) ? ei[EE + e] : (e - EE);
        float z = als[se] + ald[de];
        float lg = (z >= 0.f) ? z : 0.2f * z;
        ebuf[e] = lg;
        atomicMaxF(&nmax[de], lg);
    }
    __syncthreads();
    for (int e = t; e < ET; e += C) {
        int de = (e < EE) ? ei[EE + e] : (e - EE);
        float ex = __expf(ebuf[e] - nmax[de]);
        ebuf[e] = ex;
        atomicAdd(&nsum[de], ex);
    }
    __syncthreads();
    if (t < NN) nsum[t] = 1.f / nsum[t];
    __syncthreads();
    for (int e = t; e < ET; e += C) {
        int se = (e < EE) ? ei[e] : (e - EE);
        int de = (e < EE) ? ei[EE + e] : (e - EE);
        atomicAdd(&alphaM[de * NN + se], ebuf[e] * nsum[de]);
    }
    __syncthreads();
}

template <int C, bool RELU>
__global__ void __launch_bounds__(C) gat_agg_bf(
    const float* __restrict__ H, const int* __restrict__ ei,
    const float* __restrict__ a_s, const float* __restrict__ a_d,
    const float* __restrict__ bias,
    __nv_bfloat16* __restrict__ Ohi, __nv_bfloat16* __restrict__ Olo)
{
    __shared__ alignas(16) float hs[NN * C];
    __shared__ float als[NN], ald[NN], nmax[NN], nsum[NN];
    __shared__ float ebuf[ET];
    __shared__ float alphaM[NN * NN];

    const int t = threadIdx.x;
    const size_t gbase = (size_t)blockIdx.x * NN * C;

    if (t < NN) { nmax[t] = -1e30f; nsum[t] = 0.f; }
    for (int i = t; i < NN * NN; i += C) alphaM[i] = 0.f;
    {
        const float4* H4 = (const float4*)(H + gbase);
        float4* hs4 = (float4*)hs;
        for (int i = t; i < NN * C / 4; i += C) hs4[i] = H4[i];
    }
    __syncthreads();

    attn_alpha<C>(hs, ei, a_s, a_d, als, ald, nmax, nsum, ebuf, alphaM, t);

    float hreg[NN];
#pragma unroll
    for (int s = 0; s < NN; s++) hreg[s] = hs[s * C + t];
    const float bc = bias[t];
#pragma unroll
    for (int n = 0; n < NN; n++) {
        float acc = 0.f;
#pragma unroll
        for (int s = 0; s < NN; s++) acc += alphaM[n * NN + s] * hreg[s];
        float v = acc + bc;
        if (RELU) v = fmaxf(v, 0.f);
        __nv_bfloat16 hi = __float2bfloat16(v);
        Ohi[gbase + (size_t)n * C + t] = hi;
        Olo[gbase + (size_t)n * C + t] = __float2bfloat16(v - __bfloat162float(hi));
    }
}

// Final layer: aggregation (no relu) + fused head
__global__ void __launch_bounds__(OO) gat_final(
    const float* __restrict__ H, const int* __restrict__ ei,
    const float* __restrict__ a_s, const float* __restrict__ a_d,
    const float* __restrict__ bias, float* __restrict__ outp,
    const float* __restrict__ ws, const float* __restrict__ bsc)
{
    constexpr int C = OO;
    __shared__ alignas(16) float hs[NN * C];
    __shared__ float als[NN], ald[NN], nmax[NN], nsum[NN];
    __shared__ float ebuf[ET];
    __shared__ float alphaM[NN * NN];
    __shared__ alignas(16) float outbuf[NN * C];
    __shared__ float pbuf[C];

    const int t = threadIdx.x;
    const size_t gbase = (size_t)blockIdx.x * NN * C;

    if (t < NN) { nmax[t] = -1e30f; nsum[t] = 0.f; }
    for (int i = t; i < NN * NN; i += C) alphaM[i] = 0.f;
    {
        const float4* H4 = (const float4*)(H + gbase);
        float4* hs4 = (float4*)hs;
        for (int i = t; i < NN * C / 4; i += C) hs4[i] = H4[i];
    }
    __syncthreads();

    attn_alpha<C>(hs, ei, a_s, a_d, als, ald, nmax, nsum, ebuf, alphaM, t);

    float hreg[NN];
#pragma unroll
    for (int s = 0; s < NN; s++) hreg[s] = hs[s * C + t];
    const float bc = bias[t];
#pragma unroll
    for (int n = 0; n < NN; n++) {
        float acc = 0.f;
#pragma unroll
        for (int s = 0; s < NN; s++) acc += alphaM[n * NN + s] * hreg[s];
        outbuf[n * C + t] = acc + bc;
    }
    __syncthreads();

    {
        float pv = 0.f;
#pragma unroll
        for (int n = 0; n < NN; n++) pv += ws[n] * outbuf[n * C + t];
        pbuf[t] = pv;
    }
    __syncthreads();
    {
        const int w = t >> 5, lane = t & 31, NW = C / 32;
        const float bv = bsc[0];
        for (int n = w; n < NN; n += NW) {
            float s = 0.f;
#pragma unroll
            for (int j = 0; j < C / 32; j++)
                s += outbuf[n * C + lane + 32 * j] * pbuf[lane + 32 * j];
#pragma unroll
            for (int o = 16; o; o >>= 1)
                s += __shfl_xor_sync(0xffffffffu, s, o);
            if (lane == 0)
                outp[(size_t)blockIdx.x * NN + n] = 1.f / (1.f + __expf(-(s + bv)));
        }
    }
}

// ---------------------------------------------------------------------------
// Launch
// ---------------------------------------------------------------------------
extern "C" void kernel_launch(void* const* d_in, const int* in_sizes, int n_in,
                              void* d_out, int out_size)
{
    (void)in_sizes; (void)n_in; (void)out_size;
    const float* x   = (const float*)d_in[0];
    const int*   ei  = (const int*)  d_in[1];
    const float* W1  = (const float*)d_in[3];
    const float* as1 = (const float*)d_in[4];
    const float* ad1 = (const float*)d_in[5];
    const float* b1  = (const float*)d_in[6];
    const float* W2  = (const float*)d_in[7];
    const float* as2 = (const float*)d_in[8];
    const float* ad2 = (const float*)d_in[9];
    const float* b2  = (const float*)d_in[10];
    const float* W3  = (const float*)d_in[11];
    const float* as3 = (const float*)d_in[12];
    const float* ad3 = (const float*)d_in[13];
    const float* b3  = (const float*)d_in[14];
    const float* W4  = (const float*)d_in[15];
    const float* as4 = (const float*)d_in[16];
    const float* ad4 = (const float*)d_in[17];
    const float* b4  = (const float*)d_in[18];
    const float* ws  = (const float*)d_in[19];
    const float* bs  = (const float*)d_in[20];
    float* out = (float*)d_out;

    __nv_bfloat16 *Ahi, *Alo, *Wh, *Wl;
    float* Hb;
    cudaGetSymbolAddress((void**)&Ahi, g_Ahi);
    cudaGetSymbolAddress((void**)&Alo, g_Alo);
    cudaGetSymbolAddress((void**)&Hb,  g_H);
    cudaGetSymbolAddress((void**)&Wh,  g_Wh);
    cudaGetSymbolAddress((void**)&Wl,  g_Wl);

    cudaFuncSetAttribute(gemm_mma<FF, HH>, cudaFuncAttributeMaxDynamicSharedMemorySize, GEMM_SMEM);
    cudaFuncSetAttribute(gemm_mma<HH, HH>, cudaFuncAttributeMaxDynamicSharedMemorySize, GEMM_SMEM);
    cudaFuncSetAttribute(gemm_mma<HH, OO>, cudaFuncAttributeMaxDynamicSharedMemorySize, GEMM_SMEM);

    __nv_bfloat16* Wh0 = Wh + 0 * (HH * HH);
    __nv_bfloat16* Wh1 = Wh + 1 * (HH * HH);
    __nv_bfloat16* Wh2 = Wh + 2 * (HH * HH);
    __nv_bfloat16* Wh3 = Wh + 3 * (HH * HH);
    __nv_bfloat16* Wl0 = Wl + 0 * (HH * HH);
    __nv_bfloat16* Wl1 = Wl + 1 * (HH * HH);
    __nv_bfloat16* Wl2 = Wl + 2 * (HH * HH);
    __nv_bfloat16* Wl3 = Wl + 3 * (HH * HH);

    split_x_kernel<<<(MM * FF + 255) / 256, 256>>>(x, Ahi, Alo, (size_t)MM * FF);
    split_w_kernel<<<(FF * HH + 255) / 256, 256>>>(W1, Wh0, Wl0, FF, HH);
    split_w_kernel<<<(HH * HH + 255) / 256, 256>>>(W2, Wh1, Wl1, HH, HH);
    split_w_kernel<<<(HH * HH + 255) / 256, 256>>>(W3, Wh2, Wl2, HH, HH);
    split_w_kernel<<<(HH * OO + 255) / 256, 256>>>(W4, Wh3, Wl3, HH, OO);

    const dim3 g2(HH / 256, MM / 128);   // (2, 608)
    const dim3 g1(OO / 256, MM / 128);   // (1, 608)

    // Layer 1
    gemm_mma<FF, HH><<<g2, 256, GEMM_SMEM>>>(Ahi, Alo, Wh0, Wl0, Hb);
    gat_agg_bf<HH, true><<<BB, HH>>>(Hb, ei, as1, ad1, b1, Ahi, Alo);
    // Layer 2
    gemm_mma<HH, HH><<<g2, 256, GEMM_SMEM>>>(Ahi, Alo, Wh1, Wl1, Hb);
    gat_agg_bf<HH, true><<<BB, HH>>>(Hb, ei, as2, ad2, b2, Ahi, Alo);
    // Layer 3
    gemm_mma<HH, HH><<<g2, 256, GEMM_SMEM>>>(Ahi, Alo, Wh2, Wl2, Hb);
    gat_agg_bf<HH, true><<<BB, HH>>>(Hb, ei, as3, ad3, b3, Ahi, Alo);
    // Layer 4 + fused head
    gemm_mma<HH, OO><<<g1, 256, GEMM_SMEM>>>(Ahi, Alo, Wh3, Wl3, Hb);
    gat_final<<<BB, OO>>>(Hb, ei, as4, ad4, b4, out, ws, bs);
}